// round 13
// baseline (speedup 1.0000x reference)
#include <cuda_runtime.h>
#include <cstdint>
#include <cmath>

#define B_ 4
#define S_ 2048
#define H_ 12
#define D_ 64
#define BM 128         // q rows per CTA (4 warps x m=32)
#define BN 64          // k cols per tile
#define NKT (S_ / BN)  // 32 k-tiles
#define KST 72         // K stage row stride (words): LDS.64 bank start 8g+2tg, conflict-free
#define VST 68         // V stage row stride (words): LDS.32 bank 8tg+g, conflict-free
#define PST 72         // P row stride (words): >=64 content, LDS.64 conflict-free

#define KSTAGE (BN * KST)   // 4608 floats
#define VSTAGE (BN * VST)   // 4352 floats
#define SMEM_BYTES ((2 * KSTAGE + 2 * VSTAGE) * 4 + 128 * PST * 4)  // 108544

__device__ __forceinline__ uint32_t f2tf(float x) {
    uint32_t y;
    asm("cvt.rna.tf32.f32 %0, %1;" : "=r"(y) : "f"(x));
    return y;
}

__device__ __forceinline__ void cp16(void* dst_smem, const void* src_gmem) {
    unsigned d = (unsigned)__cvta_generic_to_shared(dst_smem);
    asm volatile("cp.async.cg.shared.global [%0], [%1], 16;\n" :: "r"(d), "l"(src_gmem));
}

__device__ __forceinline__ void mma8(float* c, const uint32_t* a, const uint32_t* b) {
    asm volatile(
        "mma.sync.aligned.m16n8k8.row.col.f32.tf32.tf32.f32 "
        "{%0,%1,%2,%3}, {%4,%5,%6,%7}, {%8,%9}, {%0,%1,%2,%3};"
        : "+f"(c[0]), "+f"(c[1]), "+f"(c[2]), "+f"(c[3])
        : "r"(a[0]), "r"(a[1]), "r"(a[2]), "r"(a[3]), "r"(b[0]), "r"(b[1]));
}

__global__ void __launch_bounds__(128)
fa2_tf32_kernel(const float* __restrict__ q, const float* __restrict__ k,
                const float* __restrict__ v, const float* __restrict__ bias,
                float* __restrict__ out)
{
    extern __shared__ float smem[];
    float* Ks = smem;                              // [2][KSTAGE] raw fp32
    float* Vs = smem + 2 * KSTAGE;                 // [2][VSTAGE] raw fp32
    float* Ps = smem + 2 * KSTAGE + 2 * VSTAGE;    // [4 warps][32 x PST] tf32 bits

    const int tid  = threadIdx.x;
    const int w    = tid >> 5;
    const int lane = tid & 31;
    const int g    = lane >> 2;   // 0..7
    const int tg   = lane & 3;    // 0..3

    const int qt = blockIdx.x;
    const int bh = blockIdx.y;
    const int b  = bh / H_;
    const int h  = bh % H_;
    const int q0 = qt * BM;

    const float scale = 0.125f;   // 1/sqrt(64)

    const float* kbase = k + ((size_t)b * S_) * (H_ * D_) + h * D_;
    const float* vbase = v + ((size_t)b * S_) * (H_ * D_) + h * D_;
    const float* bbase = bias + (((size_t)b * H_ + h) * S_ + q0 + w * 32) * (size_t)S_;

    // ---- Q fragments with PAIRED k-mapping: virtual k=tg -> col 8kf+2tg,
    //      virtual k=tg+4 -> col 8kf+2tg+1 (A/B agree; sum set per mma unchanged)
    uint32_t qa[8][8];
    {
        const float* qr[4];
        #pragma unroll
        for (int rb = 0; rb < 4; rb++)
            qr[rb] = q + ((size_t)b * S_ + q0 + w * 32 + rb * 8 + g) * (H_ * D_) + h * D_;
        #pragma unroll
        for (int kf = 0; kf < 8; kf++) {
            const int c0 = kf * 8 + 2 * tg;
            float2 q0v = *(const float2*)(qr[0] + c0);
            float2 q1v = *(const float2*)(qr[1] + c0);
            float2 q2v = *(const float2*)(qr[2] + c0);
            float2 q3v = *(const float2*)(qr[3] + c0);
            qa[kf][0] = f2tf(q0v.x); qa[kf][1] = f2tf(q1v.x);
            qa[kf][2] = f2tf(q0v.y); qa[kf][3] = f2tf(q1v.y);
            qa[kf][4] = f2tf(q2v.x); qa[kf][5] = f2tf(q3v.x);
            qa[kf][6] = f2tf(q2v.y); qa[kf][7] = f2tf(q3v.y);
        }
    }

    float o[8][8];
    #pragma unroll
    for (int nf = 0; nf < 8; nf++)
        #pragma unroll
        for (int c = 0; c < 8; c++) o[nf][c] = 0.f;

    float m_[4] = {-INFINITY, -INFINITY, -INFINITY, -INFINITY};
    float l_[4] = {0.f, 0.f, 0.f, 0.f};

    // ---- prologue: prefetch tile 0 into stage 0 ----
    #pragma unroll
    for (int i = 0; i < 8; i++) {
        const int c   = tid + i * 128;
        const int row = c >> 4;
        const int col = (c & 15) * 4;
        cp16(&Ks[row * KST + col], kbase + (size_t)row * (H_ * D_) + col);
        cp16(&Vs[row * VST + col], vbase + (size_t)row * (H_ * D_) + col);
    }
    asm volatile("cp.async.commit_group;\n" ::);

    #pragma unroll 1
    for (int kt = 0; kt < NKT; kt++) {
        const int k0 = kt * BN;
        const int s  = kt & 1;
        const float* Kf = Ks + s * KSTAGE;
        const float* Vf = Vs + s * VSTAGE;

        asm volatile("cp.async.wait_group 0;\n" ::);
        __syncthreads();   // closes all reads of stage s^1 (iteration kt-1)

        // ---- prefetch tile kt+1 into stage s^1 (after barrier: no WAR race) ----
        if (kt + 1 < NKT) {
            const int k0n = (kt + 1) * BN;
            float* Kn = Ks + (s ^ 1) * KSTAGE;
            float* Vn = Vs + (s ^ 1) * VSTAGE;
            #pragma unroll
            for (int i = 0; i < 8; i++) {
                const int c   = tid + i * 128;
                const int row = c >> 4;
                const int col = (c & 15) * 4;
                cp16(&Kn[row * KST + col], kbase + (size_t)(k0n + row) * (H_ * D_) + col);
                cp16(&Vn[row * VST + col], vbase + (size_t)(k0n + row) * (H_ * D_) + col);
            }
            asm volatile("cp.async.commit_group;\n" ::);
        }

        // ---- S = Q @ K^T : per-warp 32x64; K B-frag pairs via LDS.64 ----
        float sacc[8][8];
        #pragma unroll
        for (int nf = 0; nf < 8; nf++)
            #pragma unroll
            for (int c = 0; c < 8; c++) sacc[nf][c] = 0.f;

        #pragma unroll
        for (int kf = 0; kf < 8; kf++) {
            #pragma unroll
            for (int nf = 0; nf < 8; nf++) {
                float2 kp = *(const float2*)&Kf[(nf * 8 + g) * KST + kf * 8 + 2 * tg];
                uint32_t bk[2];
                bk[0] = f2tf(kp.x);
                bk[1] = f2tf(kp.y);
                mma8(&sacc[nf][0], &qa[kf][0], bk);
                mma8(&sacc[nf][4], &qa[kf][4], bk);
            }
        }

        // ---- scale + bias (inline loads) ----
        #pragma unroll
        for (int nf = 0; nf < 8; nf++)
            #pragma unroll
            for (int rb = 0; rb < 4; rb++) {
                float2 u = *(const float2*)(bbase + (size_t)(rb * 8 + g) * S_
                                            + k0 + nf * 8 + 2 * tg);
                sacc[nf][2 * rb]     = fmaf(sacc[nf][2 * rb],     scale, u.x);
                sacc[nf][2 * rb + 1] = fmaf(sacc[nf][2 * rb + 1], scale, u.y);
            }

        // ---- online softmax (4 rows per thread) ----
        float a_[4];
        #pragma unroll
        for (int rb = 0; rb < 4; rb++) {
            float mx = -INFINITY;
            #pragma unroll
            for (int nf = 0; nf < 8; nf++)
                mx = fmaxf(mx, fmaxf(sacc[nf][2 * rb], sacc[nf][2 * rb + 1]));
            mx = fmaxf(mx, __shfl_xor_sync(0xffffffffu, mx, 1));
            mx = fmaxf(mx, __shfl_xor_sync(0xffffffffu, mx, 2));
            const float nm = fmaxf(m_[rb], mx);
            a_[rb] = __expf(m_[rb] - nm);
            m_[rb] = nm;
        }

        float rs[4] = {0.f, 0.f, 0.f, 0.f};
        #pragma unroll
        for (int nf = 0; nf < 8; nf++)
            #pragma unroll
            for (int rb = 0; rb < 4; rb++) {
                float p0 = __expf(sacc[nf][2 * rb]     - m_[rb]);
                float p1 = __expf(sacc[nf][2 * rb + 1] - m_[rb]);
                uint32_t u0 = f2tf(p0), u1 = f2tf(p1);
                sacc[nf][2 * rb]     = __uint_as_float(u0);
                sacc[nf][2 * rb + 1] = __uint_as_float(u1);
                rs[rb] += __uint_as_float(u0) + __uint_as_float(u1);
            }
        #pragma unroll
        for (int rb = 0; rb < 4; rb++) {
            rs[rb] += __shfl_xor_sync(0xffffffffu, rs[rb], 1);
            rs[rb] += __shfl_xor_sync(0xffffffffu, rs[rb], 2);
            l_[rb] = l_[rb] * a_[rb] + rs[rb];
        }

        #pragma unroll
        for (int nf = 0; nf < 8; nf++)
            #pragma unroll
            for (int rb = 0; rb < 4; rb++) {
                o[nf][2 * rb]     *= a_[rb];
                o[nf][2 * rb + 1] *= a_[rb];
            }

        // ---- P -> warp-private smem (C-frag pairs are naturally adjacent) ----
        float* Pw = Ps + w * (32 * PST);
        #pragma unroll
        for (int rb = 0; rb < 4; rb++)
            #pragma unroll
            for (int nf = 0; nf < 8; nf++)
                *(float2*)&Pw[(rb * 8 + g) * PST + nf * 8 + 2 * tg] =
                    make_float2(sacc[nf][2 * rb], sacc[nf][2 * rb + 1]);
        __syncwarp();

        // ---- O += P @ V : P A-frag pairs via LDS.64 (paired k-mapping) ----
        #pragma unroll
        for (int kf = 0; kf < 8; kf++) {
            float2 p0 = *(const float2*)&Pw[(g)      * PST + kf * 8 + 2 * tg];
            float2 p1 = *(const float2*)&Pw[(g + 8)  * PST + kf * 8 + 2 * tg];
            float2 p2 = *(const float2*)&Pw[(g + 16) * PST + kf * 8 + 2 * tg];
            float2 p3 = *(const float2*)&Pw[(g + 24) * PST + kf * 8 + 2 * tg];
            uint32_t paA[4] = { __float_as_uint(p0.x), __float_as_uint(p1.x),
                                __float_as_uint(p0.y), __float_as_uint(p1.y) };
            uint32_t paB[4] = { __float_as_uint(p2.x), __float_as_uint(p3.x),
                                __float_as_uint(p2.y), __float_as_uint(p3.y) };
            #pragma unroll
            for (int nf = 0; nf < 8; nf++) {
                uint32_t vb[2];
                vb[0] = f2tf(Vf[(kf * 8 + 2 * tg)     * VST + nf * 8 + g]);
                vb[1] = f2tf(Vf[(kf * 8 + 2 * tg + 1) * VST + nf * 8 + g]);
                mma8(&o[nf][0], paA, vb);
                mma8(&o[nf][4], paB, vb);
            }
        }
    }

    // ---- normalize and write out ----
    float inv[4];
    #pragma unroll
    for (int rb = 0; rb < 4; rb++) inv[rb] = 1.f / l_[rb];

    #pragma unroll
    for (int rb = 0; rb < 4; rb++) {
        const int r = q0 + w * 32 + rb * 8 + g;
        float* op = out + ((size_t)b * S_ + r) * (H_ * D_) + h * D_;
        #pragma unroll
        for (int nf = 0; nf < 8; nf++)
            *(float2*)(op + nf * 8 + 2 * tg) =
                make_float2(o[nf][2 * rb] * inv[rb], o[nf][2 * rb + 1] * inv[rb]);
    }
}

extern "C" void kernel_launch(void* const* d_in, const int* in_sizes, int n_in,
                              void* d_out, int out_size)
{
    const float* q    = (const float*)d_in[0];
    const float* k    = (const float*)d_in[1];
    const float* v    = (const float*)d_in[2];
    const float* bias = (const float*)d_in[3];
    float* out = (float*)d_out;
    (void)in_sizes; (void)n_in; (void)out_size;

    cudaFuncSetAttribute(fa2_tf32_kernel,
                         cudaFuncAttributeMaxDynamicSharedMemorySize, SMEM_BYTES);

    dim3 grid(S_ / BM, B_ * H_);
    fa2_tf32_kernel<<<grid, 128, SMEM_BYTES>>>(q, k, v, bias, out);
}

// round 15
// speedup vs baseline: 1.0021x; 1.0021x over previous
#include <cuda_runtime.h>
#include <cstdint>
#include <cmath>

#define B_ 4
#define S_ 2048
#define H_ 12
#define D_ 64
#define BM 128         // q rows per CTA (4 warps x m=32)
#define BN 32          // k cols per tile
#define NKT (S_ / BN)  // 64 k-tiles
#define KST 72         // K stage row stride (words): LDS.64 start bank 8g+2tg, conflict-free
#define VST 68         // V stage row stride (words): LDS.32 bank 8(tg+nf)+g, conflict-free
#define PST 40         // P row stride (words): LDS.64 start bank 8g+2tg, conflict-free

#define KSTAGE (BN * KST)   // 2304 floats
#define VSTAGE (BN * VST)   // 2176 floats
#define SMEM_BYTES ((2 * KSTAGE + 2 * VSTAGE) * 4 + 4 * BN * PST * 4)  // 56320

__device__ __forceinline__ uint32_t f2tf(float x) {
    uint32_t y;
    asm("cvt.rna.tf32.f32 %0, %1;" : "=r"(y) : "f"(x));
    return y;
}

__device__ __forceinline__ void cp16(void* dst_smem, const void* src_gmem) {
    unsigned d = (unsigned)__cvta_generic_to_shared(dst_smem);
    asm volatile("cp.async.cg.shared.global [%0], [%1], 16;\n" :: "r"(d), "l"(src_gmem));
}

__device__ __forceinline__ void mma8(float* c, const uint32_t* a, const uint32_t* b) {
    asm volatile(
        "mma.sync.aligned.m16n8k8.row.col.f32.tf32.tf32.f32 "
        "{%0,%1,%2,%3}, {%4,%5,%6,%7}, {%8,%9}, {%0,%1,%2,%3};"
        : "+f"(c[0]), "+f"(c[1]), "+f"(c[2]), "+f"(c[3])
        : "r"(a[0]), "r"(a[1]), "r"(a[2]), "r"(a[3]), "r"(b[0]), "r"(b[1]));
}

__global__ void __launch_bounds__(128, 3)
fa2_tf32_kernel(const float* __restrict__ q, const float* __restrict__ k,
                const float* __restrict__ v, const float* __restrict__ bias,
                float* __restrict__ out)
{
    extern __shared__ float smem[];
    float* Ks = smem;                              // [2][KSTAGE] raw fp32
    float* Vs = smem + 2 * KSTAGE;                 // [2][VSTAGE] raw fp32
    float* Ps = smem + 2 * KSTAGE + 2 * VSTAGE;    // [4 warps][32 x PST] tf32 bits

    const int tid  = threadIdx.x;
    const int w    = tid >> 5;
    const int lane = tid & 31;
    const int g    = lane >> 2;   // 0..7
    const int tg   = lane & 3;    // 0..3

    const int qt = blockIdx.x;
    const int bh = blockIdx.y;
    const int b  = bh / H_;
    const int h  = bh % H_;
    const int q0 = qt * BM;

    const float scale = 0.125f;   // 1/sqrt(64)

    const float* kbase = k + ((size_t)b * S_) * (H_ * D_) + h * D_;
    const float* vbase = v + ((size_t)b * S_) * (H_ * D_) + h * D_;
    const float* bbase = bias + (((size_t)b * H_ + h) * S_ + q0 + w * 32) * (size_t)S_;
    // Q row base for this thread's fragment rows (row g of row-block 0)
    const float* qp = q + ((size_t)b * S_ + q0 + w * 32 + g) * (H_ * D_) + h * D_;

    float o[8][8];
    #pragma unroll
    for (int nf = 0; nf < 8; nf++)
        #pragma unroll
        for (int c = 0; c < 8; c++) o[nf][c] = 0.f;

    float m_[4] = {-INFINITY, -INFINITY, -INFINITY, -INFINITY};
    float l_[4] = {0.f, 0.f, 0.f, 0.f};

    // ---- prologue: prefetch tile 0 into stage 0 ----
    #pragma unroll
    for (int i = 0; i < 4; i++) {
        const int c   = tid + i * 128;
        const int row = c >> 4;
        const int col = (c & 15) * 4;
        cp16(&Ks[row * KST + col], kbase + (size_t)row * (H_ * D_) + col);
        cp16(&Vs[row * VST + col], vbase + (size_t)row * (H_ * D_) + col);
    }
    asm volatile("cp.async.commit_group;\n" ::);

    #pragma unroll 1
    for (int kt = 0; kt < NKT; kt++) {
        const int k0 = kt * BN;
        const int s  = kt & 1;
        const float* Kf = Ks + s * KSTAGE;
        const float* Vf = Vs + s * VSTAGE;

        asm volatile("cp.async.wait_group 0;\n" ::);
        __syncthreads();   // closes all reads of stage s^1 (iteration kt-1)

        // ---- prefetch tile kt+1 into stage s^1 (after barrier: no WAR race) ----
        if (kt + 1 < NKT) {
            const int k0n = (kt + 1) * BN;
            float* Kn = Ks + (s ^ 1) * KSTAGE;
            float* Vn = Vs + (s ^ 1) * VSTAGE;
            #pragma unroll
            for (int i = 0; i < 4; i++) {
                const int c   = tid + i * 128;
                const int row = c >> 4;
                const int col = (c & 15) * 4;
                cp16(&Kn[row * KST + col], kbase + (size_t)(k0n + row) * (H_ * D_) + col);
                cp16(&Vn[row * VST + col], vbase + (size_t)(k0n + row) * (H_ * D_) + col);
            }
            asm volatile("cp.async.commit_group;\n" ::);
        }

        // ---- S = Q @ K^T : per-warp 32x32; Q reloaded from gmem (L1-hot),
        //      paired-k mapping (virtual k=tg -> col 2tg, k=tg+4 -> col 2tg+1)
        float sacc[4][8];
        #pragma unroll
        for (int nf = 0; nf < 4; nf++)
            #pragma unroll
            for (int c = 0; c < 8; c++) sacc[nf][c] = 0.f;

        #pragma unroll
        for (int kf = 0; kf < 8; kf++) {
            const int c0 = kf * 8 + 2 * tg;
            float2 q0v = *(const float2*)(qp + c0);                 // row g
            float2 q1v = *(const float2*)(qp + 8  * (H_ * D_) + c0); // row g+8
            float2 q2v = *(const float2*)(qp + 16 * (H_ * D_) + c0); // row g+16
            float2 q3v = *(const float2*)(qp + 24 * (H_ * D_) + c0); // row g+24
            uint32_t qaA[4] = { f2tf(q0v.x), f2tf(q1v.x), f2tf(q0v.y), f2tf(q1v.y) };
            uint32_t qaB[4] = { f2tf(q2v.x), f2tf(q3v.x), f2tf(q2v.y), f2tf(q3v.y) };
            #pragma unroll
            for (int nf = 0; nf < 4; nf++) {
                float2 kp = *(const float2*)&Kf[(nf * 8 + g) * KST + kf * 8 + 2 * tg];
                uint32_t bk[2] = { f2tf(kp.x), f2tf(kp.y) };
                mma8(&sacc[nf][0], qaA, bk);
                mma8(&sacc[nf][4], qaB, bk);
            }
        }

        // ---- scale + bias (inline loads) ----
        #pragma unroll
        for (int nf = 0; nf < 4; nf++)
            #pragma unroll
            for (int rb = 0; rb < 4; rb++) {
                float2 u = *(const float2*)(bbase + (size_t)(rb * 8 + g) * S_
                                            + k0 + nf * 8 + 2 * tg);
                sacc[nf][2 * rb]     = fmaf(sacc[nf][2 * rb],     scale, u.x);
                sacc[nf][2 * rb + 1] = fmaf(sacc[nf][2 * rb + 1], scale, u.y);
            }

        // ---- online softmax (4 rows per thread) ----
        float a_[4];
        #pragma unroll
        for (int rb = 0; rb < 4; rb++) {
            float mx = -INFINITY;
            #pragma unroll
            for (int nf = 0; nf < 4; nf++)
                mx = fmaxf(mx, fmaxf(sacc[nf][2 * rb], sacc[nf][2 * rb + 1]));
            mx = fmaxf(mx, __shfl_xor_sync(0xffffffffu, mx, 1));
            mx = fmaxf(mx, __shfl_xor_sync(0xffffffffu, mx, 2));
            const float nm = fmaxf(m_[rb], mx);
            a_[rb] = __expf(m_[rb] - nm);
            m_[rb] = nm;
        }

        float rs[4] = {0.f, 0.f, 0.f, 0.f};
        #pragma unroll
        for (int nf = 0; nf < 4; nf++)
            #pragma unroll
            for (int rb = 0; rb < 4; rb++) {
                float p0 = __expf(sacc[nf][2 * rb]     - m_[rb]);
                float p1 = __expf(sacc[nf][2 * rb + 1] - m_[rb]);
                uint32_t u0 = f2tf(p0), u1 = f2tf(p1);
                sacc[nf][2 * rb]     = __uint_as_float(u0);
                sacc[nf][2 * rb + 1] = __uint_as_float(u1);
                rs[rb] += __uint_as_float(u0) + __uint_as_float(u1);
            }
        #pragma unroll
        for (int rb = 0; rb < 4; rb++) {
            rs[rb] += __shfl_xor_sync(0xffffffffu, rs[rb], 1);
            rs[rb] += __shfl_xor_sync(0xffffffffu, rs[rb], 2);
            l_[rb] = l_[rb] * a_[rb] + rs[rb];
        }

        #pragma unroll
        for (int nf = 0; nf < 8; nf++)
            #pragma unroll
            for (int rb = 0; rb < 4; rb++) {
                o[nf][2 * rb]     *= a_[rb];
                o[nf][2 * rb + 1] *= a_[rb];
            }

        // ---- P -> warp-private smem (C-frag pairs naturally adjacent; STS.64) ----
        float* Pw = Ps + w * (BN * PST);
        #pragma unroll
        for (int rb = 0; rb < 4; rb++)
            #pragma unroll
            for (int nf = 0; nf < 4; nf++)
                *(float2*)&Pw[(rb * 8 + g) * PST + nf * 8 + 2 * tg] =
                    make_float2(sacc[nf][2 * rb], sacc[nf][2 * rb + 1]);
        __syncwarp();

        // ---- O += P @ V : P A-frag pairs via LDS.64 (paired k-mapping) ----
        #pragma unroll
        for (int kf = 0; kf < 4; kf++) {
            float2 p0 = *(const float2*)&Pw[(g)      * PST + kf * 8 + 2 * tg];
            float2 p1 = *(const float2*)&Pw[(g + 8)  * PST + kf * 8 + 2 * tg];
            float2 p2 = *(const float2*)&Pw[(g + 16) * PST + kf * 8 + 2 * tg];
            float2 p3 = *(const float2*)&Pw[(g + 24) * PST + kf * 8 + 2 * tg];
            uint32_t paA[4] = { __float_as_uint(p0.x), __float_as_uint(p1.x),
                                __float_as_uint(p0.y), __float_as_uint(p1.y) };
            uint32_t paB[4] = { __float_as_uint(p2.x), __float_as_uint(p3.x),
                                __float_as_uint(p2.y), __float_as_uint(p3.y) };
            #pragma unroll
            for (int nf = 0; nf < 8; nf++) {
                uint32_t vb[2];
                vb[0] = f2tf(Vf[(kf * 8 + 2 * tg)     * VST + nf * 8 + g]);
                vb[1] = f2tf(Vf[(kf * 8 + 2 * tg + 1) * VST + nf * 8 + g]);
                mma8(&o[nf][0], paA, vb);
                mma8(&o[nf][4], paB, vb);
            }
        }
    }

    // ---- normalize and write out ----
    float inv[4];
    #pragma unroll
    for (int rb = 0; rb < 4; rb++) inv[rb] = 1.f / l_[rb];

    #pragma unroll
    for (int rb = 0; rb < 4; rb++) {
        const int r = q0 + w * 32 + rb * 8 + g;
        float* op = out + ((size_t)b * S_ + r) * (H_ * D_) + h * D_;
        #pragma unroll
        for (int nf = 0; nf < 8; nf++)
            *(float2*)(op + nf * 8 + 2 * tg) =
                make_float2(o[nf][2 * rb] * inv[rb], o[nf][2 * rb + 1] * inv[rb]);
    }
}

extern "C" void kernel_launch(void* const* d_in, const int* in_sizes, int n_in,
                              void* d_out, int out_size)
{
    const float* q    = (const float*)d_in[0];
    const float* k    = (const float*)d_in[1];
    const float* v    = (const float*)d_in[2];
    const float* bias = (const float*)d_in[3];
    float* out = (float*)d_out;
    (void)in_sizes; (void)n_in; (void)out_size;

    cudaFuncSetAttribute(fa2_tf32_kernel,
                         cudaFuncAttributeMaxDynamicSharedMemorySize, SMEM_BYTES);

    dim3 grid(S_ / BM, B_ * H_);
    fa2_tf32_kernel<<<grid, 128, SMEM_BYTES>>>(q, k, v, bias, out);
}

// round 16
// speedup vs baseline: 1.1745x; 1.1720x over previous
#include <cuda_runtime.h>
#include <cstdint>
#include <cmath>

#define B_ 4
#define S_ 2048
#define H_ 12
#define D_ 64
#define BM 128         // q rows per CTA (4 warps x m=32)
#define BN 32          // k cols per tile
#define NKT (S_ / BN)  // 64 k-tiles
#define QST 72         // Q smem row stride (words): LDS.64 start bank 8g+2tg, conflict-free
#define KST 72         // K row stride: LDS.64 start bank 8g+2tg, conflict-free
#define VST 68         // V row stride: LDS.32 bank 8tg+g(+8nf), conflict-free
#define PST 40         // P row stride: LDS.64 start bank 8g+2tg, conflict-free

// smem word offsets
#define Q_OFF  0
#define K_OFF  (128 * QST)               // 9216 w in
#define V_OFF  (K_OFF + BN * KST)
#define P_OFF  (V_OFF + BN * VST)
#define SMEM_WORDS (P_OFF + 128 * PST)   // 18816 words
#define SMEM_BYTES (SMEM_WORDS * 4)      // 75264 B -> 3 CTAs = 220.5 KB

__device__ __forceinline__ uint32_t f2tf(float x) {
    uint32_t y;
    asm("cvt.rna.tf32.f32 %0, %1;" : "=r"(y) : "f"(x));
    return y;
}

__device__ __forceinline__ void cp16(void* dst_smem, const void* src_gmem) {
    unsigned d = (unsigned)__cvta_generic_to_shared(dst_smem);
    asm volatile("cp.async.cg.shared.global [%0], [%1], 16;\n" :: "r"(d), "l"(src_gmem));
}

__device__ __forceinline__ void mma8(float* c, const uint32_t* a, const uint32_t* b) {
    asm volatile(
        "mma.sync.aligned.m16n8k8.row.col.f32.tf32.tf32.f32 "
        "{%0,%1,%2,%3}, {%4,%5,%6,%7}, {%8,%9}, {%0,%1,%2,%3};"
        : "+f"(c[0]), "+f"(c[1]), "+f"(c[2]), "+f"(c[3])
        : "r"(a[0]), "r"(a[1]), "r"(a[2]), "r"(a[3]), "r"(b[0]), "r"(b[1]));
}

__global__ void __launch_bounds__(128, 3)
fa2_tf32_kernel(const float* __restrict__ q, const float* __restrict__ k,
                const float* __restrict__ v, const float* __restrict__ bias,
                float* __restrict__ out)
{
    extern __shared__ float smem[];
    float* Qs = smem + Q_OFF;   // tf32 bits, pre-converted, read-only after prologue
    float* Ks = smem + K_OFF;   // raw fp32, single stage
    float* Vs = smem + V_OFF;   // raw fp32, single stage
    float* Ps = smem + P_OFF;   // tf32 bits, per-warp 32-row blocks

    const int tid  = threadIdx.x;
    const int w    = tid >> 5;
    const int lane = tid & 31;
    const int g    = lane >> 2;   // 0..7
    const int tg   = lane & 3;    // 0..3

    const int qt = blockIdx.x;
    const int bh = blockIdx.y;
    const int b  = bh / H_;
    const int h  = bh % H_;
    const int q0 = qt * BM;

    const float scale = 0.125f;   // 1/sqrt(64)

    const float* qbase = q + ((size_t)b * S_) * (H_ * D_) + h * D_;
    const float* kbase = k + ((size_t)b * S_) * (H_ * D_) + h * D_;
    const float* vbase = v + ((size_t)b * S_) * (H_ * D_) + h * D_;
    const float* bbase = bias + (((size_t)b * H_ + h) * S_ + q0 + w * 32) * (size_t)S_;

    // ---- prologue: Q tile -> smem, converted to tf32 once ----
    #pragma unroll
    for (int i = 0; i < 16; i++) {
        const int c   = tid + i * 128;
        const int row = c >> 4;
        const int col = (c & 15) * 4;
        float4 qv = *(const float4*)(qbase + (size_t)(q0 + row) * (H_ * D_) + col);
        uint4 qc = make_uint4(f2tf(qv.x), f2tf(qv.y), f2tf(qv.z), f2tf(qv.w));
        *(uint4*)&Qs[row * QST + col] = qc;
    }

    float o[8][8];
    #pragma unroll
    for (int nf = 0; nf < 8; nf++)
        #pragma unroll
        for (int c = 0; c < 8; c++) o[nf][c] = 0.f;

    float m_[4] = {-INFINITY, -INFINITY, -INFINITY, -INFINITY};
    float l_[4] = {0.f, 0.f, 0.f, 0.f};

    // Q row pointers for this warp's A-frag reads (paired-k: col 8kf+2tg, +1)
    const float* Qw = Qs + (w * 32) * QST;

    #pragma unroll 1
    for (int kt = 0; kt < NKT; kt++) {
        const int k0 = kt * BN;

        __syncthreads();   // closes previous tile's K/V (and P) smem reads; Q store on kt==0

        // ---- issue K/V(kt) into the single stage ----
        #pragma unroll
        for (int i = 0; i < 4; i++) {
            const int c   = tid + i * 128;
            const int row = c >> 4;
            const int col = (c & 15) * 4;
            cp16(&Ks[row * KST + col], kbase + (size_t)(k0 + row) * (H_ * D_) + col);
            cp16(&Vs[row * VST + col], vbase + (size_t)(k0 + row) * (H_ * D_) + col);
        }
        asm volatile("cp.async.commit_group;\n" ::);

        // ---- bias(kt) loads overlap the cp.async window ----
        float2 bz[4][4];
        #pragma unroll
        for (int rb = 0; rb < 4; rb++)
            #pragma unroll
            for (int nf = 0; nf < 4; nf++)
                bz[rb][nf] = *(const float2*)(bbase + (size_t)(rb * 8 + g) * S_
                                              + k0 + nf * 8 + 2 * tg);

        asm volatile("cp.async.wait_group 0;\n" ::);
        __syncthreads();

        // ---- S = Q @ K^T : Q from smem (pre-tf32, LDS.64), K LDS.64 + cvt ----
        float sacc[4][8];
        #pragma unroll
        for (int nf = 0; nf < 4; nf++)
            #pragma unroll
            for (int c = 0; c < 8; c++) sacc[nf][c] = 0.f;

        #pragma unroll
        for (int kf = 0; kf < 8; kf++) {
            const int c0 = kf * 8 + 2 * tg;
            float2 q0v = *(const float2*)&Qw[(g)      * QST + c0];
            float2 q1v = *(const float2*)&Qw[(g + 8)  * QST + c0];
            float2 q2v = *(const float2*)&Qw[(g + 16) * QST + c0];
            float2 q3v = *(const float2*)&Qw[(g + 24) * QST + c0];
            uint32_t qaA[4] = { __float_as_uint(q0v.x), __float_as_uint(q1v.x),
                                __float_as_uint(q0v.y), __float_as_uint(q1v.y) };
            uint32_t qaB[4] = { __float_as_uint(q2v.x), __float_as_uint(q3v.x),
                                __float_as_uint(q2v.y), __float_as_uint(q3v.y) };
            #pragma unroll
            for (int nf = 0; nf < 4; nf++) {
                float2 kp = *(const float2*)&Ks[(nf * 8 + g) * KST + c0];
                uint32_t bk[2] = { f2tf(kp.x), f2tf(kp.y) };
                mma8(&sacc[nf][0], qaA, bk);
                mma8(&sacc[nf][4], qaB, bk);
            }
        }

        // ---- scale + bias ----
        #pragma unroll
        for (int nf = 0; nf < 4; nf++)
            #pragma unroll
            for (int rb = 0; rb < 4; rb++) {
                sacc[nf][2 * rb]     = fmaf(sacc[nf][2 * rb],     scale, bz[rb][nf].x);
                sacc[nf][2 * rb + 1] = fmaf(sacc[nf][2 * rb + 1], scale, bz[rb][nf].y);
            }

        // ---- online softmax (4 rows per thread) ----
        float a_[4];
        #pragma unroll
        for (int rb = 0; rb < 4; rb++) {
            float mx = -INFINITY;
            #pragma unroll
            for (int nf = 0; nf < 4; nf++)
                mx = fmaxf(mx, fmaxf(sacc[nf][2 * rb], sacc[nf][2 * rb + 1]));
            mx = fmaxf(mx, __shfl_xor_sync(0xffffffffu, mx, 1));
            mx = fmaxf(mx, __shfl_xor_sync(0xffffffffu, mx, 2));
            const float nm = fmaxf(m_[rb], mx);
            a_[rb] = __expf(m_[rb] - nm);
            m_[rb] = nm;
        }

        float rs[4] = {0.f, 0.f, 0.f, 0.f};
        #pragma unroll
        for (int nf = 0; nf < 4; nf++)
            #pragma unroll
            for (int rb = 0; rb < 4; rb++) {
                float p0 = __expf(sacc[nf][2 * rb]     - m_[rb]);
                float p1 = __expf(sacc[nf][2 * rb + 1] - m_[rb]);
                uint32_t u0 = f2tf(p0), u1 = f2tf(p1);
                sacc[nf][2 * rb]     = __uint_as_float(u0);
                sacc[nf][2 * rb + 1] = __uint_as_float(u1);
                rs[rb] += __uint_as_float(u0) + __uint_as_float(u1);
            }
        #pragma unroll
        for (int rb = 0; rb < 4; rb++) {
            rs[rb] += __shfl_xor_sync(0xffffffffu, rs[rb], 1);
            rs[rb] += __shfl_xor_sync(0xffffffffu, rs[rb], 2);
            l_[rb] = l_[rb] * a_[rb] + rs[rb];
        }

        #pragma unroll
        for (int nf = 0; nf < 8; nf++)
            #pragma unroll
            for (int rb = 0; rb < 4; rb++) {
                o[nf][2 * rb]     *= a_[rb];
                o[nf][2 * rb + 1] *= a_[rb];
            }

        // ---- P -> warp-private smem (STS.64; C-frag pairs adjacent) ----
        float* Pw = Ps + w * (BN * PST);
        #pragma unroll
        for (int rb = 0; rb < 4; rb++)
            #pragma unroll
            for (int nf = 0; nf < 4; nf++)
                *(float2*)&Pw[(rb * 8 + g) * PST + nf * 8 + 2 * tg] =
                    make_float2(sacc[nf][2 * rb], sacc[nf][2 * rb + 1]);
        __syncwarp();

        // ---- O += P @ V : P LDS.64 (paired-k), V LDS.32 + cvt ----
        #pragma unroll
        for (int kf = 0; kf < 4; kf++) {
            float2 p0 = *(const float2*)&Pw[(g)      * PST + kf * 8 + 2 * tg];
            float2 p1 = *(const float2*)&Pw[(g + 8)  * PST + kf * 8 + 2 * tg];
            float2 p2 = *(const float2*)&Pw[(g + 16) * PST + kf * 8 + 2 * tg];
            float2 p3 = *(const float2*)&Pw[(g + 24) * PST + kf * 8 + 2 * tg];
            uint32_t paA[4] = { __float_as_uint(p0.x), __float_as_uint(p1.x),
                                __float_as_uint(p0.y), __float_as_uint(p1.y) };
            uint32_t paB[4] = { __float_as_uint(p2.x), __float_as_uint(p3.x),
                                __float_as_uint(p2.y), __float_as_uint(p3.y) };
            #pragma unroll
            for (int nf = 0; nf < 8; nf++) {
                uint32_t vb[2];
                vb[0] = f2tf(Vs[(kf * 8 + 2 * tg)     * VST + nf * 8 + g]);
                vb[1] = f2tf(Vs[(kf * 8 + 2 * tg + 1) * VST + nf * 8 + g]);
                mma8(&o[nf][0], paA, vb);
                mma8(&o[nf][4], paB, vb);
            }
        }
    }

    // ---- normalize and write out ----
    float inv[4];
    #pragma unroll
    for (int rb = 0; rb < 4; rb++) inv[rb] = 1.f / l_[rb];

    #pragma unroll
    for (int rb = 0; rb < 4; rb++) {
        const int r = q0 + w * 32 + rb * 8 + g;
        float* op = out + ((size_t)b * S_ + r) * (H_ * D_) + h * D_;
        #pragma unroll
        for (int nf = 0; nf < 8; nf++)
            *(float2*)(op + nf * 8 + 2 * tg) =
                make_float2(o[nf][2 * rb] * inv[rb], o[nf][2 * rb + 1] * inv[rb]);
    }
}

extern "C" void kernel_launch(void* const* d_in, const int* in_sizes, int n_in,
                              void* d_out, int out_size)
{
    const float* q    = (const float*)d_in[0];
    const float* k    = (const float*)d_in[1];
    const float* v    = (const float*)d_in[2];
    const float* bias = (const float*)d_in[3];
    float* out = (float*)d_out;
    (void)in_sizes; (void)n_in; (void)out_size;

    cudaFuncSetAttribute(fa2_tf32_kernel,
                         cudaFuncAttributeMaxDynamicSharedMemorySize, SMEM_BYTES);

    dim3 grid(S_ / BM, B_ * H_);
    fa2_tf32_kernel<<<grid, 128, SMEM_BYTES>>>(q, k, v, bias, out);
}

// round 17
// speedup vs baseline: 1.3089x; 1.1145x over previous
#include <cuda_runtime.h>
#include <cstdint>
#include <cmath>

#define B_ 4
#define S_ 2048
#define H_ 12
#define D_ 64
#define BM 128         // q rows per CTA (4 warps x m=32)
#define BN 32          // k cols per tile
#define NKT (S_ / BN)  // 64 k-tiles
#define QST 72         // Q smem row stride (words): LDS.64 start bank 8g+2tg, conflict-free
#define KST 72         // K row stride: LDS.64 start bank 8g+2tg, conflict-free
#define VST 68         // V row stride: LDS.32 bank 8tg+g(+8nf), conflict-free

#define KSTAGE (BN * KST)   // 2304 words
#define VSTAGE (BN * VST)   // 2176 words
// smem word offsets
#define Q_OFF  0
#define K_OFF  (128 * QST)               // 9216
#define V_OFF  (K_OFF + 2 * KSTAGE)      // 13824
#define SMEM_WORDS (V_OFF + 2 * VSTAGE)  // 18176
#define SMEM_BYTES (SMEM_WORDS * 4)      // 72704 B -> 3 CTAs = 218 KB

__device__ __forceinline__ uint32_t f2tf(float x) {
    uint32_t y;
    asm("cvt.rna.tf32.f32 %0, %1;" : "=r"(y) : "f"(x));
    return y;
}

__device__ __forceinline__ void cp16(void* dst_smem, const void* src_gmem) {
    unsigned d = (unsigned)__cvta_generic_to_shared(dst_smem);
    asm volatile("cp.async.cg.shared.global [%0], [%1], 16;\n" :: "r"(d), "l"(src_gmem));
}

__device__ __forceinline__ void mma8(float* c, const uint32_t* a, const uint32_t* b) {
    asm volatile(
        "mma.sync.aligned.m16n8k8.row.col.f32.tf32.tf32.f32 "
        "{%0,%1,%2,%3}, {%4,%5,%6,%7}, {%8,%9}, {%0,%1,%2,%3};"
        : "+f"(c[0]), "+f"(c[1]), "+f"(c[2]), "+f"(c[3])
        : "r"(a[0]), "r"(a[1]), "r"(a[2]), "r"(a[3]), "r"(b[0]), "r"(b[1]));
}

__global__ void __launch_bounds__(128, 3)
fa2_tf32_kernel(const float* __restrict__ q, const float* __restrict__ k,
                const float* __restrict__ v, const float* __restrict__ bias,
                float* __restrict__ out)
{
    extern __shared__ float smem[];
    float* Qs = smem + Q_OFF;   // tf32 bits, pre-converted, read-only after prologue
    float* Ks = smem + K_OFF;   // [2][KSTAGE] raw fp32
    float* Vs = smem + V_OFF;   // [2][VSTAGE] raw fp32

    const int tid  = threadIdx.x;
    const int w    = tid >> 5;
    const int lane = tid & 31;
    const int g    = lane >> 2;   // 0..7
    const int tg   = lane & 3;    // 0..3

    const int qt = blockIdx.x;
    const int bh = blockIdx.y;
    const int b  = bh / H_;
    const int h  = bh % H_;
    const int q0 = qt * BM;

    const float scale = 0.125f;   // 1/sqrt(64)

    const float* qbase = q + ((size_t)b * S_) * (H_ * D_) + h * D_;
    const float* kbase = k + ((size_t)b * S_) * (H_ * D_) + h * D_;
    const float* vbase = v + ((size_t)b * S_) * (H_ * D_) + h * D_;
    const float* bbase = bias + (((size_t)b * H_ + h) * S_ + q0 + w * 32) * (size_t)S_;

    // ---- prologue: Q tile -> smem (tf32, once); prefetch K/V tile 0 ----
    #pragma unroll
    for (int i = 0; i < 16; i++) {
        const int c   = tid + i * 128;
        const int row = c >> 4;
        const int col = (c & 15) * 4;
        float4 qv = *(const float4*)(qbase + (size_t)(q0 + row) * (H_ * D_) + col);
        *(uint4*)&Qs[row * QST + col] =
            make_uint4(f2tf(qv.x), f2tf(qv.y), f2tf(qv.z), f2tf(qv.w));
    }
    #pragma unroll
    for (int i = 0; i < 4; i++) {
        const int c   = tid + i * 128;
        const int row = c >> 4;
        const int col = (c & 15) * 4;
        cp16(&Ks[row * KST + col], kbase + (size_t)row * (H_ * D_) + col);
        cp16(&Vs[row * VST + col], vbase + (size_t)row * (H_ * D_) + col);
    }
    asm volatile("cp.async.commit_group;\n" ::);

    float o[8][8];
    #pragma unroll
    for (int nf = 0; nf < 8; nf++)
        #pragma unroll
        for (int c = 0; c < 8; c++) o[nf][c] = 0.f;

    float m_[4] = {-INFINITY, -INFINITY, -INFINITY, -INFINITY};
    float l_[4] = {0.f, 0.f, 0.f, 0.f};

    const float* Qw = Qs + (w * 32) * QST;

    #pragma unroll 1
    for (int kt = 0; kt < NKT; kt++) {
        const int k0 = kt * BN;
        const int s  = kt & 1;
        const float* Kf = Ks + s * KSTAGE;
        const float* Vf = Vs + s * VSTAGE;

        asm volatile("cp.async.wait_group 0;\n" ::);
        __syncthreads();   // K/V(kt) visible; closes reads of stage s^1; Q stores on kt==0

        // ---- prefetch K/V(kt+1) into stage s^1 (after barrier: no WAR race) ----
        if (kt + 1 < NKT) {
            const int k0n = (kt + 1) * BN;
            float* Kn = Ks + (s ^ 1) * KSTAGE;
            float* Vn = Vs + (s ^ 1) * VSTAGE;
            #pragma unroll
            for (int i = 0; i < 4; i++) {
                const int c   = tid + i * 128;
                const int row = c >> 4;
                const int col = (c & 15) * 4;
                cp16(&Kn[row * KST + col], kbase + (size_t)(k0n + row) * (H_ * D_) + col);
                cp16(&Vn[row * VST + col], vbase + (size_t)(k0n + row) * (H_ * D_) + col);
            }
            asm volatile("cp.async.commit_group;\n" ::);
        }

        // ---- bias loads issued early (overlap QK mma) ----
        float2 bz[4][4];
        #pragma unroll
        for (int rb = 0; rb < 4; rb++)
            #pragma unroll
            for (int nf = 0; nf < 4; nf++)
                bz[rb][nf] = *(const float2*)(bbase + (size_t)(rb * 8 + g) * S_
                                              + k0 + nf * 8 + 2 * tg);

        // ---- S = Q @ K^T : Q pre-tf32 LDS.64, K LDS.64 + cvt; paired-k ----
        float sacc[4][8];
        #pragma unroll
        for (int nf = 0; nf < 4; nf++)
            #pragma unroll
            for (int c = 0; c < 8; c++) sacc[nf][c] = 0.f;

        #pragma unroll
        for (int kf = 0; kf < 8; kf++) {
            const int c0 = kf * 8 + 2 * tg;
            float2 q0v = *(const float2*)&Qw[(g)      * QST + c0];
            float2 q1v = *(const float2*)&Qw[(g + 8)  * QST + c0];
            float2 q2v = *(const float2*)&Qw[(g + 16) * QST + c0];
            float2 q3v = *(const float2*)&Qw[(g + 24) * QST + c0];
            uint32_t qaA[4] = { __float_as_uint(q0v.x), __float_as_uint(q1v.x),
                                __float_as_uint(q0v.y), __float_as_uint(q1v.y) };
            uint32_t qaB[4] = { __float_as_uint(q2v.x), __float_as_uint(q3v.x),
                                __float_as_uint(q2v.y), __float_as_uint(q3v.y) };
            #pragma unroll
            for (int nf = 0; nf < 4; nf++) {
                float2 kp = *(const float2*)&Kf[(nf * 8 + g) * KST + c0];
                uint32_t bk[2] = { f2tf(kp.x), f2tf(kp.y) };
                mma8(&sacc[nf][0], qaA, bk);
                mma8(&sacc[nf][4], qaB, bk);
            }
        }

        // ---- scale + bias ----
        // sacc[nf][0]=(row g, col 2tg) [1]=(g,2tg+1) [2]=(g+8,2tg) [3]=(g+8,2tg+1)
        // sacc[nf][4..7] same with rows g+16/g+24.
        #pragma unroll
        for (int nf = 0; nf < 4; nf++) {
            sacc[nf][0] = fmaf(sacc[nf][0], scale, bz[0][nf].x);
            sacc[nf][1] = fmaf(sacc[nf][1], scale, bz[0][nf].y);
            sacc[nf][2] = fmaf(sacc[nf][2], scale, bz[1][nf].x);
            sacc[nf][3] = fmaf(sacc[nf][3], scale, bz[1][nf].y);
            sacc[nf][4] = fmaf(sacc[nf][4], scale, bz[2][nf].x);
            sacc[nf][5] = fmaf(sacc[nf][5], scale, bz[2][nf].y);
            sacc[nf][6] = fmaf(sacc[nf][6], scale, bz[3][nf].x);
            sacc[nf][7] = fmaf(sacc[nf][7], scale, bz[3][nf].y);
        }

        // ---- online softmax: row-blocks rb=0..3 live at sacc[][{2rb,2rb+1}] ----
        float a_[4];
        #pragma unroll
        for (int rb = 0; rb < 4; rb++) {
            float mx = -INFINITY;
            #pragma unroll
            for (int nf = 0; nf < 4; nf++)
                mx = fmaxf(mx, fmaxf(sacc[nf][2 * rb], sacc[nf][2 * rb + 1]));
            mx = fmaxf(mx, __shfl_xor_sync(0xffffffffu, mx, 1));
            mx = fmaxf(mx, __shfl_xor_sync(0xffffffffu, mx, 2));
            const float nm = fmaxf(m_[rb], mx);
            a_[rb] = __expf(m_[rb] - nm);
            m_[rb] = nm;
        }

        float rs[4] = {0.f, 0.f, 0.f, 0.f};
        #pragma unroll
        for (int nf = 0; nf < 4; nf++)
            #pragma unroll
            for (int rb = 0; rb < 4; rb++) {
                float p0 = __expf(sacc[nf][2 * rb]     - m_[rb]);
                float p1 = __expf(sacc[nf][2 * rb + 1] - m_[rb]);
                uint32_t u0 = f2tf(p0), u1 = f2tf(p1);
                sacc[nf][2 * rb]     = __uint_as_float(u0);
                sacc[nf][2 * rb + 1] = __uint_as_float(u1);
                rs[rb] += __uint_as_float(u0) + __uint_as_float(u1);
            }
        #pragma unroll
        for (int rb = 0; rb < 4; rb++) {
            rs[rb] += __shfl_xor_sync(0xffffffffu, rs[rb], 1);
            rs[rb] += __shfl_xor_sync(0xffffffffu, rs[rb], 2);
            l_[rb] = l_[rb] * a_[rb] + rs[rb];
        }

        #pragma unroll
        for (int nf = 0; nf < 8; nf++)
            #pragma unroll
            for (int rb = 0; rb < 4; rb++) {
                o[nf][2 * rb]     *= a_[rb];
                o[nf][2 * rb + 1] *= a_[rb];
            }

        // ---- O += P @ V : P stays in registers!
        // C-frag {c0,c1,c2,c3} -> A-frag {c0,c2,c1,c3} under paired-k mapping.
        #pragma unroll
        for (int kf = 0; kf < 4; kf++) {
            uint32_t paA[4] = { __float_as_uint(sacc[kf][0]), __float_as_uint(sacc[kf][2]),
                                __float_as_uint(sacc[kf][1]), __float_as_uint(sacc[kf][3]) };
            uint32_t paB[4] = { __float_as_uint(sacc[kf][4]), __float_as_uint(sacc[kf][6]),
                                __float_as_uint(sacc[kf][5]), __float_as_uint(sacc[kf][7]) };
            #pragma unroll
            for (int nf = 0; nf < 8; nf++) {
                uint32_t vb[2];
                vb[0] = f2tf(Vf[(kf * 8 + 2 * tg)     * VST + nf * 8 + g]);
                vb[1] = f2tf(Vf[(kf * 8 + 2 * tg + 1) * VST + nf * 8 + g]);
                mma8(&o[nf][0], paA, vb);
                mma8(&o[nf][4], paB, vb);
            }
        }
    }

    // ---- normalize and write out ----
    float inv[4];
    #pragma unroll
    for (int rb = 0; rb < 4; rb++) inv[rb] = 1.f / l_[rb];

    #pragma unroll
    for (int rb = 0; rb < 4; rb++) {
        const int r = q0 + w * 32 + rb * 8 + g;
        float* op = out + ((size_t)b * S_ + r) * (H_ * D_) + h * D_;
        #pragma unroll
        for (int nf = 0; nf < 8; nf++)
            *(float2*)(op + nf * 8 + 2 * tg) =
                make_float2(o[nf][2 * rb] * inv[rb], o[nf][2 * rb + 1] * inv[rb]);
    }
}

extern "C" void kernel_launch(void* const* d_in, const int* in_sizes, int n_in,
                              void* d_out, int out_size)
{
    const float* q    = (const float*)d_in[0];
    const float* k    = (const float*)d_in[1];
    const float* v    = (const float*)d_in[2];
    const float* bias = (const float*)d_in[3];
    float* out = (float*)d_out;
    (void)in_sizes; (void)n_in; (void)out_size;

    cudaFuncSetAttribute(fa2_tf32_kernel,
                         cudaFuncAttributeMaxDynamicSharedMemorySize, SMEM_BYTES);

    dim3 grid(S_ / BM, B_ * H_);
    fa2_tf32_kernel<<<grid, 128, SMEM_BYTES>>>(q, k, v, bias, out);
}